// round 8
// baseline (speedup 1.0000x reference)
#include <cuda_runtime.h>
#include <cstdint>

#define HH 96
#define WW 96
#define HW (HH*WW)
#define NB 8
#define SLICES 8
#define NBLK (NB*2*SLICES)       // 128 blocks: (sample, dir, slice)
#define NTHR 576                 // 2*288: one thread per (image, mask word); 18 warps
#define PTS_PER_BLK (HW/SLICES)  // 1152 = 576 * 2
#define NWORDS (HH*3)            // 288 mask words per image

__device__ unsigned g_max[NB];        // per-sample result, float bits (>=0); self-reset
__device__ int      g_done_s[NB];     // per-sample arrival counters (to 16); self-reset
__device__ int      g_done = 0;       // sample-group counter (to 8); self-reset

// Branchless nearest set-bit distance to column c in a 96-bit row (one LDS.128).
// Returns >= WW if the row is empty on both sides.
__device__ __forceinline__ int row_nearest_dx(const uint32_t* __restrict__ base, int y,
                                              uint32_t mR0, uint32_t mR1, uint32_t mR2,
                                              uint32_t mL0, uint32_t mL1, uint32_t mL2,
                                              int c)
{
    const uint4 row = *(const uint4*)(base + y * 4);
    const uint32_t r0 = row.x & mR0, r1 = row.y & mR1, r2 = row.z & mR2;
    int pR = r0 ? (__ffs(r0) - 1) : 1000;
    pR = min(pR, r1 ? (__ffs(r1) + 31) : 1000);
    pR = min(pR, r2 ? (__ffs(r2) + 63) : 1000);
    const uint32_t l0 = row.x & mL0, l1 = row.y & mL1, l2 = row.z & mL2;
    int pL = l0 ? (31 - __clz(l0)) : -1000;
    pL = max(pL, l1 ? (63 - __clz(l1)) : -1000);
    pL = max(pL, l2 ? (95 - __clz(l2)) : -1000);
    return min(pR - c, c - pL);
}

__global__ void __launch_bounds__(NTHR)
hausdorff_kernel(const float* __restrict__ pred,
                 const float* __restrict__ targ,
                 float* __restrict__ out)
{
    __shared__ uint32_t s_A[HH * 4];  // stride-4 rows, words 0..2 used, word 3 = 0
    __shared__ uint32_t s_B[HH * 4];
    __shared__ float    s_red[NTHR / 32];

    const int blk   = blockIdx.x;
    const int slice = blk & (SLICES - 1);
    const int nd    = blk >> 3;           // n*2 + dir
    const int dir   = nd & 1;
    const int n     = nd >> 1;

    const int tid  = threadIdx.x;
    const int lane = tid & 31;
    const int warp = tid >> 5;

    // ---- Mask build: one thread per (image, word). 8 independent LDG.128 each.
    // inputs uniform [0,1): round(x) > 0.5  <=>  x > 0.5f  (0.5 ties round-even -> 0)
    {
        const int img  = (tid >= NWORDS);            // 0 -> pred/A, 1 -> targ/B
        const int t    = tid - img * NWORDS;
        const int row  = t / 3;
        const int wcol = t - row * 3;
        const float* src = img ? targ : pred;
        const float4* p4 = (const float4*)(src + n * HW) + row * 24 + wcol * 8;

        float4 v[8];
        #pragma unroll
        for (int j = 0; j < 8; ++j) v[j] = p4[j];    // 8 independent LDG.128

        uint32_t w = 0u;
        #pragma unroll
        for (int j = 0; j < 8; ++j) {
            w |= ((v[j].x > 0.5f ? 1u : 0u) | (v[j].y > 0.5f ? 2u : 0u)
                | (v[j].z > 0.5f ? 4u : 0u) | (v[j].w > 0.5f ? 8u : 0u)) << (4 * j);
        }
        uint32_t* dst = img ? s_B : s_A;
        dst[row * 4 + wcol] = w;
        if (wcol == 0) dst[row * 4 + 3] = 0u;        // zero pad word 3
    }
    __syncthreads();

    // dir 0: src = A & ~B, tgt = B;  dir 1: src = B & ~A, tgt = A
    const uint32_t* s_srcp = dir ? s_B : s_A;
    const uint32_t* s_tgt  = dir ? s_A : s_B;

    float lmax = -1.0f;   // max SQUARED distance; -1 = no src point seen

    #pragma unroll
    for (int k = 0; k < 2; ++k) {                    // 1152 = 576 * 2
        const int p = slice * PTS_PER_BLK + tid + k * NTHR;
        const int r = p / WW;
        const int c = p - r * WW;
        const int k0 = c >> 5;
        const int s  = c & 31;
        const uint32_t sw = s_srcp[r * 4 + k0] & ~s_tgt[r * 4 + k0];
        if (!((sw >> s) & 1u)) continue;

        // per-word right/left masks around column c (branchless selects)
        const uint32_t full = 0xFFFFFFFFu;
        const uint32_t hiR  = full << s;             // bits >= c within word k0
        const uint32_t loL  = (2u << s) - 1u;        // bits <= c within word k0 (s=31 -> full)
        const uint32_t mR0 = (k0 == 0) ? hiR : 0u;
        const uint32_t mR1 = (k0 < 1) ? full : ((k0 == 1) ? hiR : 0u);
        const uint32_t mR2 = (k0 < 2) ? full : hiR;
        const uint32_t mL0 = (k0 > 0) ? full : loL;
        const uint32_t mL1 = (k0 > 1) ? full : ((k0 == 1) ? loL : 0u);
        const uint32_t mL2 = (k0 == 2) ? loL : 0u;

        int best = 0x7FFFFFFF;

        // ---- Fast path: all rows |dy| <= 3, loads batched (7 independent LDS.128)
        {
            const int dx0 = row_nearest_dx(s_tgt, r, mR0, mR1, mR2, mL0, mL1, mL2, c);
            if (dx0 < WW) best = dx0 * dx0;
            #pragma unroll
            for (int dy = 1; dy <= 3; ++dy) {
                const int yu = r - dy, yd = r + dy;
                int dxu = row_nearest_dx(s_tgt, max(yu, 0),      mR0, mR1, mR2, mL0, mL1, mL2, c);
                int dxd = row_nearest_dx(s_tgt, min(yd, HH - 1), mR0, mR1, mR2, mL0, mL1, mL2, c);
                dxu = (yu >= 0) ? dxu : 10000;
                dxd = (yd < HH) ? dxd : 10000;
                const int m = min(dxu, dxd);
                if (m < WW) best = min(best, dy * dy + m * m);
            }
        }

        // ---- Rare fallback: rows |dy| >= 4 can only matter if best > 16
        if (best > 16) {
            for (int d = 4; d < HH; ++d) {
                const int dd = d * d;
                if (dd >= best) break;
                const int yu = r - d, yd = r + d;
                if (yu >= 0) {
                    const int dx = row_nearest_dx(s_tgt, yu, mR0, mR1, mR2, mL0, mL1, mL2, c);
                    if (dx < WW) best = min(best, dd + dx * dx);
                }
                if (yd < HH && dd < best) {
                    const int dx = row_nearest_dx(s_tgt, yd, mR0, mR1, mR2, mL0, mL1, mL2, c);
                    if (dx < WW) best = min(best, dd + dx * dx);
                }
            }
        }

        // squared domain; 3e9 sentinel = "target set empty" (> any real squared dist)
        const float fsq = (best == 0x7FFFFFFF) ? 3e9f : (float)best;
        lmax = fmaxf(lmax, fsq);
    }

    // block max reduction (18 warps) -- squared domain
    for (int off = 16; off; off >>= 1)
        lmax = fmaxf(lmax, __shfl_xor_sync(0xFFFFFFFFu, lmax, off));
    if (lane == 0) s_red[warp] = lmax;
    __syncthreads();

    if (tid == 0) {
        float bm = s_red[0];
        #pragma unroll
        for (int i = 1; i < NTHR / 32; ++i) bm = fmaxf(bm, s_red[i]);
        // convert: empty src -> 0; empty tgt -> 1e9 (matches reference); else sqrt/96
        float v;
        if (bm < 0.0f)        v = 0.0f;
        else if (bm > 2e9f)   v = 1e9f;
        else                  v = sqrtf(bm) * (1.0f / 96.0f);
        atomicMax(&g_max[n], __float_as_uint(v));   // valid: all values >= 0
        __threadfence();
        // hierarchical completion: 16 blocks per sample, then 8 samples
        const int ps = atomicAdd(&g_done_s[n], 1);
        if (ps == 2 * SLICES - 1) {
            g_done_s[n] = 0;                        // reset own sample counter
            __threadfence();
            const int pg = atomicAdd(&g_done, 1);
            if (pg == NB - 1) {
                __threadfence();
                volatile unsigned* gm = g_max;
                float sum = 0.0f;
                #pragma unroll
                for (int i = 0; i < NB; ++i) sum += __uint_as_float(gm[i]);
                out[0] = sum * (1.0f / NB);
                #pragma unroll
                for (int i = 0; i < NB; ++i) gm[i] = 0u;  // reset for next replay
                g_done = 0;
            }
        }
    }
}

extern "C" void kernel_launch(void* const* d_in, const int* in_sizes, int n_in,
                              void* d_out, int out_size)
{
    (void)in_sizes; (void)n_in; (void)out_size;
    const float* pred = (const float*)d_in[0];
    const float* targ = (const float*)d_in[1];
    hausdorff_kernel<<<NBLK, NTHR>>>(pred, targ, (float*)d_out);
}

// round 9
// speedup vs baseline: 1.7642x; 1.7642x over previous
#include <cuda_runtime.h>
#include <cstdint>

#define HH 96
#define WW 96
#define HW (HH*WW)
#define NB 8
#define SLICES 8
#define NBLK (NB*2*SLICES)       // 128 blocks: (sample, dir, slice)
#define NTHR 256
#define PTS_PER_BLK (HW/SLICES)  // 1152
#define NWORDS (HH*3)            // 288 mask words per image

__device__ unsigned g_max[NB];        // per-sample result, float bits (>=0); self-reset
__device__ int      g_done_s[NB];     // per-sample arrival counters (to 16); self-reset
__device__ int      g_done = 0;       // sample-group counter (to 8); self-reset

__device__ __forceinline__ uint32_t pack16(uint32_t x) {
    // one valid low-nibble per byte -> compact to 16 contiguous bits
    x = (x | (x >> 4)) & 0x00FF00FFu;
    return (x | (x >> 8)) & 0x0000FFFFu;
}

// Branchless nearest set-bit distance to column c in a 96-bit row (row preloaded).
// Returns >= WW if row empty on both sides.
__device__ __forceinline__ int nearest_in_row(uint4 row,
                                              uint32_t mR0, uint32_t mR1, uint32_t mR2,
                                              uint32_t mL0, uint32_t mL1, uint32_t mL2,
                                              int c)
{
    const uint32_t r0 = row.x & mR0, r1 = row.y & mR1, r2 = row.z & mR2;
    int pR = r0 ? (__ffs(r0) - 1) : 1000;
    pR = min(pR, r1 ? (__ffs(r1) + 31) : 1000);
    pR = min(pR, r2 ? (__ffs(r2) + 63) : 1000);
    const uint32_t l0 = row.x & mL0, l1 = row.y & mL1, l2 = row.z & mL2;
    int pL = l0 ? (31 - __clz(l0)) : -1000;
    pL = max(pL, l1 ? (63 - __clz(l1)) : -1000);
    pL = max(pL, l2 ? (95 - __clz(l2)) : -1000);
    return min(pR - c, c - pL);
}

__global__ void __launch_bounds__(NTHR)
hausdorff_kernel(const float* __restrict__ pred,
                 const float* __restrict__ targ,
                 float* __restrict__ out)
{
    __shared__ uint32_t s_nib[HW / 16];  // 576 words: one nibble-pair byte per float4
    __shared__ uint32_t s_A[HH * 4];     // stride-4 rows, words 0..2 used, word 3 = 0
    __shared__ uint32_t s_B[HH * 4];
    __shared__ float    s_red[NTHR / 32];

    const int blk   = blockIdx.x;
    const int slice = blk & (SLICES - 1);
    const int nd    = blk >> 3;          // n*2 + dir
    const int dir   = nd & 1;
    const int n     = nd >> 1;

    const int tid  = threadIdx.x;
    const int lane = tid & 31;
    const int warp = tid >> 5;

    const float4* pA4 = (const float4*)(pred + n * HW);
    const float4* pB4 = (const float4*)(targ + n * HW);

    // ---- Phase 1: coalesced loads, stage 1 byte per float4 (A low nibble, B high)
    // inputs uniform [0,1): round(x) > 0.5  <=>  x > 0.5f  (0.5 ties round-even -> 0)
    uint8_t* nb = (uint8_t*)s_nib;
    #pragma unroll
    for (int k = 0; k < 9; ++k) {
        const int idx4 = tid + k * NTHR;
        const float4 a = pA4[idx4];
        const float4 b = pB4[idx4];
        uint32_t nibA = (a.x > 0.5f ? 1u : 0u) | (a.y > 0.5f ? 2u : 0u)
                      | (a.z > 0.5f ? 4u : 0u) | (a.w > 0.5f ? 8u : 0u);
        uint32_t nibB = (b.x > 0.5f ? 1u : 0u) | (b.y > 0.5f ? 2u : 0u)
                      | (b.z > 0.5f ? 4u : 0u) | (b.w > 0.5f ? 8u : 0u);
        nb[idx4] = (uint8_t)(nibA | (nibB << 4));
    }
    __syncthreads();

    // ---- Phase 2: assemble 32-bit mask words (8 staged bytes each), no atomics
    for (int t = tid; t < NWORDS; t += NTHR) {
        const uint2 w = ((const uint2*)s_nib)[t];
        const uint32_t a0 = w.x & 0x0F0F0F0Fu, a1 = w.y & 0x0F0F0F0Fu;
        const uint32_t b0 = (w.x >> 4) & 0x0F0F0F0Fu, b1 = (w.y >> 4) & 0x0F0F0F0Fu;
        const int row = t / 3;
        const int wi  = row * 4 + (t - row * 3);
        s_A[wi] = pack16(a0) | (pack16(a1) << 16);
        s_B[wi] = pack16(b0) | (pack16(b1) << 16);
        if (wi - row * 4 == 0) { s_A[row * 4 + 3] = 0u; s_B[row * 4 + 3] = 0u; }
    }
    __syncthreads();

    // dir 0: src = A & ~B, tgt = B;  dir 1: src = B & ~A, tgt = A
    const uint32_t* s_srcp = dir ? s_B : s_A;
    const uint32_t* s_tgt  = dir ? s_A : s_B;

    float lmax = -1.0f;   // max SQUARED distance; -1 = no src point seen

    const int pend = (slice + 1) * PTS_PER_BLK;
    for (int p = slice * PTS_PER_BLK + tid; p < pend; p += NTHR) {
        const int r = p / WW;
        const int c = p - r * WW;
        const int k0 = c >> 5;
        const int s  = c & 31;
        const uint32_t sw = s_srcp[r * 4 + k0] & ~s_tgt[r * 4 + k0];
        if (!((sw >> s) & 1u)) continue;

        // per-word right/left masks around column c (branchless selects)
        const uint32_t full = 0xFFFFFFFFu;
        const uint32_t hiR  = full << s;          // bits >= c within word k0
        const uint32_t loL  = (2u << s) - 1u;     // bits <= c within word k0
        const uint32_t mR0 = (k0 == 0) ? hiR : 0u;
        const uint32_t mR1 = (k0 < 1) ? full : ((k0 == 1) ? hiR : 0u);
        const uint32_t mR2 = (k0 < 2) ? full : hiR;
        const uint32_t mL0 = (k0 > 0) ? full : loL;
        const uint32_t mL1 = (k0 > 1) ? full : ((k0 == 1) ? loL : 0u);
        const uint32_t mL2 = (k0 == 2) ? loL : 0u;

        int best = 0x7FFFFFFF;

        // ---- Fast path: rows |dy| <= 1, 3 independent LDS.128 in one latency round
        {
            const int yu = r - 1, yd = r + 1;
            const uint4 rm = *(const uint4*)(s_tgt + r * 4);
            const uint4 ru = *(const uint4*)(s_tgt + max(yu, 0) * 4);
            const uint4 rd = *(const uint4*)(s_tgt + min(yd, HH - 1) * 4);
            const int dx0 = nearest_in_row(rm, mR0, mR1, mR2, mL0, mL1, mL2, c);
            if (dx0 < WW) best = dx0 * dx0;
            int dxu = nearest_in_row(ru, mR0, mR1, mR2, mL0, mL1, mL2, c);
            int dxd = nearest_in_row(rd, mR0, mR1, mR2, mL0, mL1, mL2, c);
            dxu = (yu >= 0) ? dxu : 10000;
            dxd = (yd < HH) ? dxd : 10000;
            const int m = min(dxu, dxd);
            if (m < WW) best = min(best, 1 + m * m);
        }

        // ---- Serial early-exit for rows |dy| >= 2 (only matters if best > 4)
        if (best > 4) {
            for (int d = 2; d < HH; ++d) {
                const int dd = d * d;
                if (dd >= best) break;
                const int yu = r - d, yd = r + d;
                if (yu >= 0) {
                    const uint4 row = *(const uint4*)(s_tgt + yu * 4);
                    const int dx = nearest_in_row(row, mR0, mR1, mR2, mL0, mL1, mL2, c);
                    if (dx < WW) best = min(best, dd + dx * dx);
                }
                if (yd < HH && dd < best) {
                    const uint4 row = *(const uint4*)(s_tgt + yd * 4);
                    const int dx = nearest_in_row(row, mR0, mR1, mR2, mL0, mL1, mL2, c);
                    if (dx < WW) best = min(best, dd + dx * dx);
                }
            }
        }

        // squared domain; 3e9 sentinel = "target set empty" (> any real squared dist)
        const float fsq = (best == 0x7FFFFFFF) ? 3e9f : (float)best;
        lmax = fmaxf(lmax, fsq);
    }

    // block max reduction (8 warps) -- squared domain
    for (int off = 16; off; off >>= 1)
        lmax = fmaxf(lmax, __shfl_xor_sync(0xFFFFFFFFu, lmax, off));
    if (lane == 0) s_red[warp] = lmax;
    __syncthreads();

    if (tid == 0) {
        float bm = s_red[0];
        #pragma unroll
        for (int i = 1; i < NTHR / 32; ++i) bm = fmaxf(bm, s_red[i]);
        // convert: empty src -> 0; empty tgt -> 1e9 (matches reference); else sqrt/96
        float v;
        if (bm < 0.0f)        v = 0.0f;
        else if (bm > 2e9f)   v = 1e9f;
        else                  v = sqrtf(bm) * (1.0f / 96.0f);
        atomicMax(&g_max[n], __float_as_uint(v));   // valid: all values >= 0
        __threadfence();
        // hierarchical completion: 16 blocks per sample, then 8 samples
        const int ps = atomicAdd(&g_done_s[n], 1);
        if (ps == 2 * SLICES - 1) {
            g_done_s[n] = 0;
            __threadfence();
            const int pg = atomicAdd(&g_done, 1);
            if (pg == NB - 1) {
                __threadfence();
                volatile unsigned* gm = g_max;
                float sum = 0.0f;
                #pragma unroll
                for (int i = 0; i < NB; ++i) sum += __uint_as_float(gm[i]);
                out[0] = sum * (1.0f / NB);
                #pragma unroll
                for (int i = 0; i < NB; ++i) gm[i] = 0u;  // reset for next replay
                g_done = 0;
            }
        }
    }
}

extern "C" void kernel_launch(void* const* d_in, const int* in_sizes, int n_in,
                              void* d_out, int out_size)
{
    (void)in_sizes; (void)n_in; (void)out_size;
    const float* pred = (const float*)d_in[0];
    const float* targ = (const float*)d_in[1];
    hausdorff_kernel<<<NBLK, NTHR>>>(pred, targ, (float*)d_out);
}

// round 12
// speedup vs baseline: 1.8297x; 1.0372x over previous
#include <cuda_runtime.h>
#include <cstdint>

#define HH 96
#define WW 96
#define HW (HH*WW)
#define NB 8
#define SLICES 8
#define NBLK (NB*2*SLICES)       // 128 blocks: (sample, dir, slice)
#define NTHR 384                 // 12 warps; 1152 = 384*3 search pts, 2304 = 384*6 float4
#define PTS_PER_BLK (HW/SLICES)  // 1152
#define NWORDS (HH*3)            // 288 mask words per image

__device__ float g_partials[NBLK];   // per-block directed-distance result (>=0)
__device__ int   g_done = 0;         // completion counter; self-reset

__device__ __forceinline__ uint32_t pack16(uint32_t x) {
    // one valid low-nibble per byte -> compact to 16 contiguous bits
    x = (x | (x >> 4)) & 0x00FF00FFu;
    return (x | (x >> 8)) & 0x0000FFFFu;
}

// Branchless nearest set-bit distance to column c in a 96-bit row (row preloaded).
// Returns >= WW if row empty on both sides.
__device__ __forceinline__ int nearest_in_row(uint4 row,
                                              uint32_t mR0, uint32_t mR1, uint32_t mR2,
                                              uint32_t mL0, uint32_t mL1, uint32_t mL2,
                                              int c)
{
    const uint32_t r0 = row.x & mR0, r1 = row.y & mR1, r2 = row.z & mR2;
    int pR = r0 ? (__ffs(r0) - 1) : 1000;
    pR = min(pR, r1 ? (__ffs(r1) + 31) : 1000);
    pR = min(pR, r2 ? (__ffs(r2) + 63) : 1000);
    const uint32_t l0 = row.x & mL0, l1 = row.y & mL1, l2 = row.z & mL2;
    int pL = l0 ? (31 - __clz(l0)) : -1000;
    pL = max(pL, l1 ? (63 - __clz(l1)) : -1000);
    pL = max(pL, l2 ? (95 - __clz(l2)) : -1000);
    return min(pR - c, c - pL);
}

__global__ void __launch_bounds__(NTHR)
hausdorff_kernel(const float* __restrict__ pred,
                 const float* __restrict__ targ,
                 float* __restrict__ out)
{
    __shared__ uint32_t s_nib[HW / 16];  // 576 words: one nibble-pair byte per float4
    __shared__ uint32_t s_A[HH * 4];     // stride-4 rows, words 0..2 used, word 3 = 0
    __shared__ uint32_t s_B[HH * 4];
    __shared__ float    s_red[NTHR / 32];
    __shared__ float    s_fin[NB];
    __shared__ int      s_last;

    const int blk   = blockIdx.x;
    const int slice = blk & (SLICES - 1);
    const int nd    = blk >> 3;          // n*2 + dir
    const int dir   = nd & 1;
    const int n     = nd >> 1;

    const int tid  = threadIdx.x;
    const int lane = tid & 31;
    const int warp = tid >> 5;

    if (tid == 0) s_last = 0;

    const float4* pA4 = (const float4*)(pred + n * HW);
    const float4* pB4 = (const float4*)(targ + n * HW);

    // ---- Phase 1: coalesced loads, stage 1 byte per float4 (A low nibble, B high)
    // inputs uniform [0,1): round(x) > 0.5  <=>  x > 0.5f  (0.5 ties round-even -> 0)
    uint8_t* nb = (uint8_t*)s_nib;
    #pragma unroll
    for (int k = 0; k < 6; ++k) {        // 2304 float4 = 384 * 6
        const int idx4 = tid + k * NTHR;
        const float4 a = pA4[idx4];
        const float4 b = pB4[idx4];
        uint32_t nibA = (a.x > 0.5f ? 1u : 0u) | (a.y > 0.5f ? 2u : 0u)
                      | (a.z > 0.5f ? 4u : 0u) | (a.w > 0.5f ? 8u : 0u);
        uint32_t nibB = (b.x > 0.5f ? 1u : 0u) | (b.y > 0.5f ? 2u : 0u)
                      | (b.z > 0.5f ? 4u : 0u) | (b.w > 0.5f ? 8u : 0u);
        nb[idx4] = (uint8_t)(nibA | (nibB << 4));
    }
    __syncthreads();

    // ---- Phase 2: assemble 32-bit mask words (8 staged bytes each), one per thread
    if (tid < NWORDS) {
        const uint2 w = ((const uint2*)s_nib)[tid];
        const uint32_t a0 = w.x & 0x0F0F0F0Fu, a1 = w.y & 0x0F0F0F0Fu;
        const uint32_t b0 = (w.x >> 4) & 0x0F0F0F0Fu, b1 = (w.y >> 4) & 0x0F0F0F0Fu;
        const int row  = tid / 3;
        const int wcol = tid - row * 3;
        const int wi   = row * 4 + wcol;
        s_A[wi] = pack16(a0) | (pack16(a1) << 16);
        s_B[wi] = pack16(b0) | (pack16(b1) << 16);
        if (wcol == 0) { s_A[row * 4 + 3] = 0u; s_B[row * 4 + 3] = 0u; }
    }
    __syncthreads();

    // dir 0: src = A & ~B, tgt = B;  dir 1: src = B & ~A, tgt = A
    const uint32_t* s_srcp = dir ? s_B : s_A;
    const uint32_t* s_tgt  = dir ? s_A : s_B;

    float lmax = -1.0f;   // max SQUARED distance; -1 = no src point seen

    #pragma unroll
    for (int k = 0; k < 3; ++k) {        // 1152 = 384 * 3
        const int p = slice * PTS_PER_BLK + tid + k * NTHR;
        const int r = p / WW;
        const int c = p - r * WW;
        const int k0 = c >> 5;
        const int s  = c & 31;
        const uint32_t sw = s_srcp[r * 4 + k0] & ~s_tgt[r * 4 + k0];
        if (!((sw >> s) & 1u)) continue;

        // per-word right/left masks around column c (branchless selects)
        const uint32_t full = 0xFFFFFFFFu;
        const uint32_t hiR  = full << s;          // bits >= c within word k0
        const uint32_t loL  = (2u << s) - 1u;     // bits <= c within word k0
        const uint32_t mR0 = (k0 == 0) ? hiR : 0u;
        const uint32_t mR1 = (k0 < 1) ? full : ((k0 == 1) ? hiR : 0u);
        const uint32_t mR2 = (k0 < 2) ? full : hiR;
        const uint32_t mL0 = (k0 > 0) ? full : loL;
        const uint32_t mL1 = (k0 > 1) ? full : ((k0 == 1) ? loL : 0u);
        const uint32_t mL2 = (k0 == 2) ? loL : 0u;

        int best = 0x7FFFFFFF;

        // ---- Fast path: rows |dy| <= 1, 3 independent LDS.128 in one latency round
        {
            const int yu = r - 1, yd = r + 1;
            const uint4 rm = *(const uint4*)(s_tgt + r * 4);
            const uint4 ru = *(const uint4*)(s_tgt + max(yu, 0) * 4);
            const uint4 rd = *(const uint4*)(s_tgt + min(yd, HH - 1) * 4);
            const int dx0 = nearest_in_row(rm, mR0, mR1, mR2, mL0, mL1, mL2, c);
            if (dx0 < WW) best = dx0 * dx0;
            int dxu = nearest_in_row(ru, mR0, mR1, mR2, mL0, mL1, mL2, c);
            int dxd = nearest_in_row(rd, mR0, mR1, mR2, mL0, mL1, mL2, c);
            dxu = (yu >= 0) ? dxu : 10000;
            dxd = (yd < HH) ? dxd : 10000;
            const int m = min(dxu, dxd);
            if (m < WW) best = min(best, 1 + m * m);
        }

        // ---- Serial early-exit for rows |dy| >= 2 (only matters if best > 4)
        if (best > 4) {
            for (int d = 2; d < HH; ++d) {
                const int dd = d * d;
                if (dd >= best) break;
                const int yu = r - d, yd = r + d;
                if (yu >= 0) {
                    const uint4 row = *(const uint4*)(s_tgt + yu * 4);
                    const int dx = nearest_in_row(row, mR0, mR1, mR2, mL0, mL1, mL2, c);
                    if (dx < WW) best = min(best, dd + dx * dx);
                }
                if (yd < HH && dd < best) {
                    const uint4 row = *(const uint4*)(s_tgt + yd * 4);
                    const int dx = nearest_in_row(row, mR0, mR1, mR2, mL0, mL1, mL2, c);
                    if (dx < WW) best = min(best, dd + dx * dx);
                }
            }
        }

        // squared domain; 3e9 sentinel = "target set empty" (> any real squared dist)
        const float fsq = (best == 0x7FFFFFFF) ? 3e9f : (float)best;
        lmax = fmaxf(lmax, fsq);
    }

    // block max reduction (12 warps) -- squared domain
    for (int off = 16; off; off >>= 1)
        lmax = fmaxf(lmax, __shfl_xor_sync(0xFFFFFFFFu, lmax, off));
    if (lane == 0) s_red[warp] = lmax;
    __syncthreads();

    if (tid == 0) {
        float bm = s_red[0];
        #pragma unroll
        for (int i = 1; i < NTHR / 32; ++i) bm = fmaxf(bm, s_red[i]);
        // convert: empty src -> 0; empty tgt -> 1e9 (matches reference); else sqrt/96
        float v;
        if (bm < 0.0f)        v = 0.0f;
        else if (bm > 2e9f)   v = 1e9f;
        else                  v = sqrtf(bm) * (1.0f / 96.0f);
        g_partials[blk] = v;                       // plain STG, no round-trip
        __threadfence();
        const int prev = atomicAdd(&g_done, 1);
        if (prev == NBLK - 1) { s_last = 1; g_done = 0; }
    }
    __syncthreads();

    // ---- Parallel finisher: only the last-arriving block takes this path
    if (s_last) {
        float v = 0.0f;
        if (tid < NBLK)
            v = *(volatile float*)&g_partials[tid];   // 128 parallel L2 loads
        if (warp < NBLK / 32) {
            // 16 consecutive partials = one (sample, dir); dirs are adjacent pairs.
            // Max over each 16-lane half gives max over both dirs x 8 slices = sample result.
            #pragma unroll
            for (int off = 8; off; off >>= 1)
                v = fmaxf(v, __shfl_xor_sync(0xFFFFFFFFu, v, off));
            if ((lane & 15) == 0)
                s_fin[(warp << 1) | (lane >> 4)] = v;  // 8 sample results
        }
        __syncthreads();
        if (tid == 0) {
            float sum = 0.0f;
            #pragma unroll
            for (int i = 0; i < NB; ++i) sum += s_fin[i];
            out[0] = sum * (1.0f / NB);
        }
    }
}

extern "C" void kernel_launch(void* const* d_in, const int* in_sizes, int n_in,
                              void* d_out, int out_size)
{
    (void)in_sizes; (void)n_in; (void)out_size;
    const float* pred = (const float*)d_in[0];
    const float* targ = (const float*)d_in[1];
    hausdorff_kernel<<<NBLK, NTHR>>>(pred, targ, (float*)d_out);
}